// round 16
// baseline (speedup 1.0000x reference)
#include <cuda_runtime.h>
#include <cuda_fp16.h>
#include <cstdint>

#define N_ROWS   131072
#define KCODES   1024
#define DIMV     64
#define RPB      128                 // rows per vq CTA
#define NBLOCKS  (N_ROWS / RPB)      // 1024
#define THREADS  256
#define EPS_GAP  2.5e-2f
#define MGN      3.2e-2f             // fixup candidate window vs screen best
#define FT_CAND  32
#define GR       32                  // flagged rows per fixup group
#define NFIX     256                 // fixup CTAs
#define AMB_CAP  131072

// vq smem: B0 16K @0, B1 16K @16384 (overlay the fp32 z stage zstage[64][132]
// = 33792B @0). C[1024] fp32 @33792. Tail stage: qs[128*65] @0 (33280B),
// kss[128] @33280, wsum @33792 (overlays dead C). Total 37888.
#define ZS_STRIDE 132
#define C_OFF     33792
#define SMEM_VQ   (33792 + 4096)

__device__ float   g_e2[KCODES];
__device__ __half  g_ehi[KCODES * DIMV];
__device__ float   g_part[NBLOCKS];
__device__ float   g_corr[NFIX];
__device__ float   g_bv[N_ROWS];
__device__ int     g_idx[N_ROWS];
__device__ int     g_amb[AMB_CAP];
__device__ int     g_namb;

// ---------------- helpers ----------------
__device__ __forceinline__ void mma_f16(float* d, uint32_t a0, uint32_t a1,
                                        uint32_t a2, uint32_t a3,
                                        uint32_t b0, uint32_t b1) {
    asm volatile(
        "mma.sync.aligned.m16n8k16.row.col.f32.f16.f16.f32 "
        "{%0,%1,%2,%3}, {%4,%5,%6,%7}, {%8,%9}, {%0,%1,%2,%3};"
        : "+f"(d[0]), "+f"(d[1]), "+f"(d[2]), "+f"(d[3])
        : "r"(a0), "r"(a1), "r"(a2), "r"(a3), "r"(b0), "r"(b1));
}
__device__ __forceinline__ uint32_t smem_u32(const void* p) {
    uint32_t a;
    asm("{ .reg .u64 t; cvta.to.shared.u64 t, %1; cvt.u32.u64 %0, t; }" : "=r"(a) : "l"(p));
    return a;
}
__device__ __forceinline__ void cp16(uint32_t s, const void* g) {
    asm volatile("cp.async.cg.shared.global [%0], [%1], 16;" :: "r"(s), "l"(g));
}
__device__ __forceinline__ uint32_t pack_h2(float lo, float hi) {
    __half2 t = __floats2half2_rn(lo, hi);
    return *(uint32_t*)&t;
}

// ---------------- prep: e2 + fp16 codebook + reset ----------------
__global__ void prep_kernel(const float* __restrict__ emb) {
    if (blockIdx.x == 0 && threadIdx.x == 0) g_namb = 0;
    if (blockIdx.x == 0) g_corr[threadIdx.x] = 0.f;
    int k = blockIdx.x * 256 + threadIdx.x;
    if (k < KCODES) {
        float s = 0.f;
#pragma unroll
        for (int d = 0; d < DIMV; ++d) {
            float v = emb[k * DIMV + d];
            s = fmaf(v, v, s);
            g_ehi[k * DIMV + d] = __float2half_rn(v);
        }
        g_e2[k] = s;
    }
}

// merge (best,sec,idx) over disjoint code sets; ties force sec=best (-> fixup)
__device__ __forceinline__ void merge_bsi(float& b, float& s, int& i,
                                          float ob, float os, int oi) {
    if (ob < b)      { s = fminf(b, os); b = ob; i = oi; }
    else if (b < ob) { s = fminf(s, ob); }
    else             { i = min(i, oi); s = b; }
}

// ---------------- main screen: 2-pass fp16 HMMA + argmin + fused output/loss ----------------
__global__ __launch_bounds__(THREADS, 2) void vq_kernel(
    const float* __restrict__ z, const float* __restrict__ emb,
    float* __restrict__ out)
{
    extern __shared__ char smem[];
    const uint32_t sb = smem_u32(smem);
    const int tid  = threadIdx.x;
    const int wid  = tid >> 5;
    const int lane = tid & 31;
    const int qr   = lane >> 2;          // 0..7
    const int qc   = lane & 3;           // 0..3

    const int n0 = blockIdx.x * RPB;
    const int b  = n0 >> 12;
    const int hw = n0 & 4095;
    const int zbase = b * 262144 + hw;

    float* zsp = (float*)smem;           // [64][ZS_STRIDE], prologue only

#pragma unroll
    for (int i = 0; i < 8; ++i) {
        int idx4 = i * THREADS + tid;
        int d = idx4 >> 5, r4 = (idx4 & 31) << 2;
        float4 v = *(const float4*)(z + zbase + d * 4096 + r4);
        *(float4*)&zsp[d * ZS_STRIDE + r4] = v;
    }
    __syncthreads();

    uint32_t ah[4][4], al[4][4];
#pragma unroll
    for (int ks = 0; ks < 4; ++ks)
#pragma unroll
        for (int rg = 0; rg < 4; ++rg) {
            int r = wid * 16 + (rg & 1) * 8 + qr;
            int d = ks * 16 + (rg >> 1) * 8 + qc * 2;
            float v0 = zsp[d * ZS_STRIDE + r];
            float v1 = zsp[(d + 1) * ZS_STRIDE + r];
            float h0 = __half2float(__float2half_rn(v0));
            float h1 = __half2float(__float2half_rn(v1));
            ah[ks][rg] = pack_h2(h0, h1);
            al[ks][rg] = pack_h2(v0 - h0, v1 - h1);
        }
    __syncthreads();   // zstage dead; B bufs overwrite it

    float* csm = (float*)(smem + C_OFF);
#pragma unroll
    for (int i = 0; i < 4; ++i) csm[i * 256 + tid] = g_e2[i * 256 + tid];

    auto issue_chunk = [&](int c, int bi) {
        uint32_t bbuf = sb + bi * 16384;
#pragma unroll
        for (int i = 0; i < 4; ++i) {
            int idx = i * THREADS + tid;
            int cr = idx >> 3, u = idx & 7;
            uint32_t doff = cr * 128 + ((u ^ (cr & 7)) << 4);
            cp16(bbuf + doff, (const char*)g_ehi + c * 16384 + idx * 16);
        }
        asm volatile("cp.async.commit_group;" ::: "memory");
    };

    issue_chunk(0, 0);
    issue_chunk(1, 1);

    float best[2], sec[2];
    int   bidx[2];
#pragma unroll
    for (int g = 0; g < 2; ++g) { best[g] = 3.4028235e38f; sec[g] = 3.4028235e38f; bidx[g] = 0; }

    for (int c = 0; c < 8; ++c) {
        if (c < 7) asm volatile("cp.async.wait_group 1;" ::: "memory");
        else       asm volatile("cp.async.wait_group 0;" ::: "memory");
        __syncthreads();

        const char* bb = smem + (c & 1) * 16384;
        const int cbase = c * 128;
#pragma unroll
        for (int s = 0; s < 2; ++s) {
            float acc[8][4];
#pragma unroll
            for (int a = 0; a < 8; ++a)
#pragma unroll
                for (int q = 0; q < 4; ++q) acc[a][q] = 0.f;

#pragma unroll
            for (int ks = 0; ks < 4; ++ks) {
#pragma unroll
                for (int a = 0; a < 8; ++a) {
                    uint32_t rowoff = (uint32_t)(s * 64 + a * 8 + qr) * 128 + qc * 4;
                    uint32_t u0 = (uint32_t)(((ks * 2)     ^ qr) << 4);
                    uint32_t u1 = (uint32_t)(((ks * 2 + 1) ^ qr) << 4);
                    uint32_t b0 = *(const uint32_t*)(bb + rowoff + u0);
                    uint32_t b1 = *(const uint32_t*)(bb + rowoff + u1);
                    mma_f16(acc[a], ah[ks][0], ah[ks][1], ah[ks][2], ah[ks][3], b0, b1);
                    mma_f16(acc[a], al[ks][0], al[ks][1], al[ks][2], al[ks][3], b0, b1);
                }
            }
#pragma unroll
            for (int a = 0; a < 8; ++a) {
                int k0 = cbase + s * 64 + a * 8 + qc * 2;
                float2 cv = *(const float2*)(smem + C_OFF + k0 * 4);
                float s00 = fmaf(-2.f, acc[a][0], cv.x);
                float s01 = fmaf(-2.f, acc[a][1], cv.y);
                float s10 = fmaf(-2.f, acc[a][2], cv.x);
                float s11 = fmaf(-2.f, acc[a][3], cv.y);
                if (s00 < best[0]) { sec[0] = best[0]; best[0] = s00; bidx[0] = k0; } else if (s00 < sec[0]) sec[0] = s00;
                if (s01 < best[0]) { sec[0] = best[0]; best[0] = s01; bidx[0] = k0 + 1; } else if (s01 < sec[0]) sec[0] = s01;
                if (s10 < best[1]) { sec[1] = best[1]; best[1] = s10; bidx[1] = k0; } else if (s10 < sec[1]) sec[1] = s10;
                if (s11 < best[1]) { sec[1] = best[1]; best[1] = s11; bidx[1] = k0 + 1; } else if (s11 < sec[1]) sec[1] = s11;
            }
        }
        __syncthreads();
        if (c + 2 < 8) issue_chunk(c + 2, c & 1);
    }

#pragma unroll
    for (int off = 1; off <= 2; off <<= 1) {
#pragma unroll
        for (int g = 0; g < 2; ++g) {
            float ob = __shfl_xor_sync(0xffffffffu, best[g], off);
            float os = __shfl_xor_sync(0xffffffffu, sec[g],  off);
            int   oi = __shfl_xor_sync(0xffffffffu, bidx[g], off);
            merge_bsi(best[g], sec[g], bidx[g], ob, os, oi);
        }
    }

    // tail smem overlays (B bufs dead after last chunk's trailing sync)
    float* qs  = (float*)smem;                 // 128*65 floats = 33280B
    int*   kss = (int*)(smem + 33280);         // 128 ints
    float* wsum = (float*)(smem + C_OFF);      // overlays dead C

    if (qc == 0) {
#pragma unroll
        for (int g = 0; g < 2; ++g) {
            int rl = wid * 16 + g * 8 + qr;
            int n = n0 + rl;
            g_idx[n] = bidx[g];
            g_bv[n]  = best[g];
            kss[rl]  = bidx[g];
            if (sec[g] - best[g] < EPS_GAP) {
                int slot = atomicAdd(&g_namb, 1);
                if (slot < AMB_CAP) g_amb[slot] = n;
            }
        }
    }
    __syncthreads();

    // gather code rows via smem (coalesced emb reads, L2-resident)
    for (int rr = wid; rr < 128; rr += 8) {
        float2 e2v = ((const float2*)(emb + kss[rr] * DIMV))[lane];
        qs[rr * 65 + lane * 2]     = e2v.x;
        qs[rr * 65 + lane * 2 + 1] = e2v.y;
    }
    __syncthreads();

    float lsum = 0.f;
#pragma unroll
    for (int i = 0; i < 32; ++i) {
        int idx = i * THREADS + tid;
        int d = idx >> 7, r = idx & 127;
        float q = qs[r * 65 + d];
        int g = zbase + d * 4096 + r;
        out[g] = q;
        float diff = q - __ldg(&z[g]);
        lsum = fmaf(diff, diff, lsum);
    }
#pragma unroll
    for (int o = 16; o > 0; o >>= 1)
        lsum += __shfl_down_sync(0xffffffffu, lsum, o);
    if (lane == 0) wsum[wid] = lsum;
    __syncthreads();
    if (tid == 0) {
        float s = 0.f;
#pragma unroll
        for (int w = 0; w < 8; ++w) s += wsum[w];
        g_part[blockIdx.x] = s;
    }
}

// ---------------- single-pass batched fixup + output patch + loss correction ----------------
__global__ __launch_bounds__(256) void fixup_kernel(
    const float* __restrict__ z, const float* __restrict__ emb,
    float* __restrict__ out)
{
    __shared__ float es[128 * 68];        // 34816B code tile (conflict-free)
    __shared__ float zs[GR * 64];         // 8192B
    __shared__ float e2t[128];
    __shared__ int   rown[GR];
    __shared__ int   cnt[GR];
    __shared__ int   cand[GR * FT_CAND];  // 4096B
    __shared__ float corr8[256];          // per-thread loss-correction partials

    const int tid = threadIdx.x;
    const int r   = tid >> 3;             // row in group
    const int sub = tid & 7;

    float cacc = 0.f;
    int namb = min(g_namb, AMB_CAP);
    int ngroups = (namb + GR - 1) / GR;

    for (int grp = blockIdx.x; grp < ngroups; grp += gridDim.x) {
        int base  = grp * GR;
        int nrows = min(GR, namb - base);
        if (tid < GR) {
            rown[tid] = g_amb[base + (tid < nrows ? tid : 0)];
            cnt[tid]  = 0;
        }
        __syncthreads();

#pragma unroll
        for (int i = 0; i < 8; ++i) {
            int idx = i * 256 + tid;
            int rr = idx >> 6, d = idx & 63;
            int n = rown[rr];
            zs[rr * 64 + d] = z[(n >> 12) * 262144 + d * 4096 + (n & 4095)];
        }
        __syncthreads();

        float4 zf[16];
        float z2 = 0.f;
#pragma unroll
        for (int i = 0; i < 16; ++i) {
            zf[i] = *(const float4*)&zs[r * 64 + i * 4];
            z2 = fmaf(zf[i].x, zf[i].x, z2);
            z2 = fmaf(zf[i].y, zf[i].y, z2);
            z2 = fmaf(zf[i].z, zf[i].z, z2);
            z2 = fmaf(zf[i].w, zf[i].w, z2);
        }
        const int   n   = rown[r];
        const float thr = z2 + g_bv[n] + MGN;

        // ---- single sweep: collect candidates below threshold ----
        for (int t = 0; t < 8; ++t) {
#pragma unroll
            for (int i = 0; i < 8; ++i) {
                int idx4 = i * 256 + tid;
                int code = idx4 >> 4, d4 = idx4 & 15;
                float4 v = *(const float4*)(emb + (t * 128 + code) * 64 + d4 * 4);
                *(float4*)&es[code * 68 + d4 * 4] = v;
            }
            if (tid < 128) e2t[tid] = g_e2[t * 128 + tid];
            __syncthreads();
#pragma unroll
            for (int j = 0; j < 16; ++j) {
                int c = j * 8 + sub;
                const float4* ef = (const float4*)&es[c * 68];
                float acc = 0.f;
#pragma unroll
                for (int i = 0; i < 16; ++i) {
                    float4 e = ef[i];
                    acc = fmaf(zf[i].x, e.x, acc);
                    acc = fmaf(zf[i].y, e.y, acc);
                    acc = fmaf(zf[i].z, e.z, acc);
                    acc = fmaf(zf[i].w, e.w, acc);
                }
                float d = fmaf(-2.f, acc, z2 + e2t[c]);
                if (d < thr) {
                    int slot = atomicAdd(&cnt[r], 1);
                    if (slot < FT_CAND) cand[r * FT_CAND + slot] = t * 128 + c;
                }
            }
            __syncthreads();
        }

        // ---- fp64 exact decision over candidates ----
        int nc = min(cnt[r], FT_CAND);
        double bv = 1e300; int bk = 0x7fffffff;
        for (int q = sub; q < nc; q += 8) {
            int k = cand[r * FT_CAND + q];
            const float* e = emb + k * DIMV;
            double s = 0.0;
#pragma unroll
            for (int i = 0; i < 16; ++i) {
                double d0 = (double)zf[i].x - (double)e[i * 4 + 0]; s = fma(d0, d0, s);
                double d1 = (double)zf[i].y - (double)e[i * 4 + 1]; s = fma(d1, d1, s);
                double d2 = (double)zf[i].z - (double)e[i * 4 + 2]; s = fma(d2, d2, s);
                double d3 = (double)zf[i].w - (double)e[i * 4 + 3]; s = fma(d3, d3, s);
            }
            if (s < bv || (s == bv && k < bk)) { bv = s; bk = k; }
        }
#pragma unroll
        for (int o = 1; o < 8; o <<= 1) {
            double ov = __shfl_xor_sync(0xffffffffu, bv, o);
            int    ok = __shfl_xor_sync(0xffffffffu, bk, o);
            if (ov < bv || (ov == bv && ok < bk)) { bv = ov; bk = ok; }
        }

        // ---- patch output + loss correction for rows whose index changed ----
        int oldk = g_idx[n];
        float cp = 0.f;
        if (r < nrows && bk != oldk) {
            const float* eo = emb + oldk * DIMV + sub * 8;
            const float* en = emb + bk   * DIMV + sub * 8;
            int gb = (n >> 12) * 262144 + (n & 4095);
#pragma unroll
            for (int j = 0; j < 8; ++j) {
                int d = sub * 8 + j;
                float zv = ((const float*)&zf[d >> 2])[d & 3];
                float qo = eo[j], qn = en[j];
                float dn = qn - zv, dold = qo - zv;
                cp += dn * dn - dold * dold;
                out[gb + d * 4096] = qn;
            }
            if (sub == 0) g_idx[n] = bk;
        }
        corr8[tid] = cp;
        __syncthreads();
        if (tid == 0) {
            float s = 0.f;
            for (int i = 0; i < 256; ++i) s += corr8[i];
            cacc += s;
        }
        __syncthreads();
    }
    if (tid == 0) g_corr[blockIdx.x] = cacc;
}

__global__ void loss_kernel(float* __restrict__ out, int loss_off) {
    __shared__ float s[256];
    int t = threadIdx.x;
    s[t] = g_part[t] + g_part[t + 256] + g_part[t + 512] + g_part[t + 768]
         + g_corr[t];
    __syncthreads();
    for (int o = 128; o > 0; o >>= 1) {
        if (t < o) s[t] += s[t + o];
        __syncthreads();
    }
    if (t == 0) {
        float m = s[0] * (1.0f / 8388608.0f);
        out[loss_off] = fmaf(0.25f, m, m);
    }
}

extern "C" void kernel_launch(void* const* d_in, const int* in_sizes, int n_in,
                              void* d_out, int out_size) {
    const float* z   = (const float*)d_in[0];
    const float* emb = (const float*)d_in[1];
    float* out = (float*)d_out;
    cudaFuncSetAttribute(vq_kernel, cudaFuncAttributeMaxDynamicSharedMemorySize, SMEM_VQ);
    prep_kernel<<<4, 256>>>(emb);
    vq_kernel<<<NBLOCKS, THREADS, SMEM_VQ>>>(z, emb, out);
    fixup_kernel<<<NFIX, 256>>>(z, emb, out);
    loss_kernel<<<1, 256>>>(out, out_size - 1);
}